// round 1
// baseline (speedup 1.0000x reference)
#include <cuda_runtime.h>
#include <math.h>

// ---------------- static device scratch (no allocations allowed) ----------------
// im2col matrix: M=6400 (b*25+p), K=4608 (ci*9+ky*3+kx)
__device__ float g_col[6400 * 4608];          // 118 MB
// activations a (post BN+sigmoid): [b][i=p*32+a]  (800 per batch)
__device__ float g_a[256 * 800];
// pose (post BN): [m=b*25+p][512]
__device__ float g_pose[6400 * 512];
// votes: [b][i][c][d]  (d=16 contiguous)
__device__ float g_v[(size_t)256 * 800 * 10 * 16];  // 131 MB

#define LN2PI_F 1.8378770664093453f
#define BN_EPS_F 1e-5f
#define EPS_F 1e-12f

// ---------------- im2col ----------------
// grid: (6400, 18), block 256.  k = by*256+tid in [0,4608)
__global__ void im2col_k(const float* __restrict__ x)
{
    int k = blockIdx.y * 256 + threadIdx.x;
    int m = blockIdx.x;
    int ci = k / 9; int rem = k - ci * 9;
    int ky = rem / 3; int kx = rem - ky * 3;
    int b = m / 25; int p = m - b * 25;
    int y = p / 5;  int x0 = p - y * 5;
    int yy = y + ky - 1, xx = x0 + kx - 1;
    float v = 0.f;
    if ((unsigned)yy < 5u && (unsigned)xx < 5u)
        v = x[((b * 512 + ci) * 5 + yy) * 5 + xx];
    g_col[(size_t)m * 4608 + k] = v;
}

// ---------------- fused conv GEMM + BN (+sigmoid for a-channels) ----------------
// Out[m][n] = sum_k col[m][k] * W[n][k];  n<32 -> a conv, else pose conv (co=n-32)
// BM=128, BN=64, BK=16, 256 threads, 8x4 per-thread tile.
#define GBM 128
#define GBN 64
#define GBK 16

__global__ __launch_bounds__(256) void conv_gemm(
    const float* __restrict__ wa, const float* __restrict__ wp,
    const float* __restrict__ bag, const float* __restrict__ bab,
    const float* __restrict__ bam, const float* __restrict__ bav,
    const float* __restrict__ bpg, const float* __restrict__ bpb,
    const float* __restrict__ bpm, const float* __restrict__ bpv)
{
    __shared__ float As[GBK][GBM + 4];
    __shared__ float Bs[GBK][GBN + 4];

    int tid = threadIdx.x;
    int m0 = blockIdx.x * GBM;
    int n0 = blockIdx.y * GBN;
    int tx = tid & 15;   // 16 -> 64 cols (4 each)
    int ty = tid >> 4;   // 16 -> 128 rows (8 each)

    float acc[8][4];
#pragma unroll
    for (int i = 0; i < 8; i++)
#pragma unroll
        for (int j = 0; j < 4; j++) acc[i][j] = 0.f;

    int lrow  = tid >> 2;        // 0..63
    int lcol4 = (tid & 3) * 4;   // 0,4,8,12

    for (int k0 = 0; k0 < 4608; k0 += GBK) {
        // A tile: 128 x 16
#pragma unroll
        for (int it = 0; it < 2; it++) {
            int r = lrow + it * 64;
            float4 va = *(const float4*)&g_col[(size_t)(m0 + r) * 4608 + k0 + lcol4];
            As[lcol4 + 0][r] = va.x;
            As[lcol4 + 1][r] = va.y;
            As[lcol4 + 2][r] = va.z;
            As[lcol4 + 3][r] = va.w;
        }
        // B tile: 64 x 16
        {
            int n = n0 + lrow;
            float4 vb = make_float4(0.f, 0.f, 0.f, 0.f);
            if (n < 544) {
                const float* brow = (n < 32) ? (wa + (size_t)n * 4608)
                                             : (wp + (size_t)(n - 32) * 4608);
                vb = *(const float4*)&brow[k0 + lcol4];
            }
            Bs[lcol4 + 0][lrow] = vb.x;
            Bs[lcol4 + 1][lrow] = vb.y;
            Bs[lcol4 + 2][lrow] = vb.z;
            Bs[lcol4 + 3][lrow] = vb.w;
        }
        __syncthreads();

#pragma unroll
        for (int kk = 0; kk < GBK; kk++) {
            float a[8], bvals[4];
#pragma unroll
            for (int i = 0; i < 8; i++) a[i] = As[kk][ty * 8 + i];
#pragma unroll
            for (int j = 0; j < 4; j++) bvals[j] = Bs[kk][tx * 4 + j];
#pragma unroll
            for (int i = 0; i < 8; i++)
#pragma unroll
                for (int j = 0; j < 4; j++)
                    acc[i][j] = fmaf(a[i], bvals[j], acc[i][j]);
        }
        __syncthreads();
    }

    // epilogue: BN (+sigmoid for a), scatter to g_a / g_pose
#pragma unroll
    for (int i = 0; i < 8; i++) {
        int m = m0 + ty * 8 + i;           // always < 6400 (50 exact tiles)
        int b = m / 25, p = m - b * 25;
#pragma unroll
        for (int j = 0; j < 4; j++) {
            int n = n0 + tx * 4 + j;
            if (n >= 544) continue;
            float val = acc[i][j];
            if (n < 32) {
                float sc = bag[n] * rsqrtf(bav[n] + BN_EPS_F);
                val = (val - bam[n]) * sc + bab[n];
                g_a[b * 800 + p * 32 + n] = 1.f / (1.f + expf(-val));
            } else {
                int co = n - 32;
                float sc = bpg[co] * rsqrtf(bpv[co] + BN_EPS_F);
                val = (val - bpm[co]) * sc + bpb[co];
                g_pose[(size_t)m * 512 + co] = val;
            }
        }
    }
}

// ---------------- votes: v[b][i][c][r*4+s] = M_i(4x4) @ W[i][c](4x4) ----------------
// one thread per (b,i,c); t = (b*800+i)*10+c
__global__ __launch_bounds__(256) void votes_k(const float* __restrict__ W)
{
    int t = blockIdx.x * blockDim.x + threadIdx.x;
    if (t >= 256 * 800 * 10) return;
    int c  = t % 10;
    int bi = t / 10;
    int i  = bi % 800;
    int b  = bi / 800;
    int a  = i & 31, p = i >> 5;

    const float* mp = g_pose + (size_t)(b * 25 + p) * 512 + a * 16;
    float M[16];
#pragma unroll
    for (int q = 0; q < 4; q++) {
        float4 v4 = *(const float4*)(mp + q * 4);
        M[q * 4 + 0] = v4.x; M[q * 4 + 1] = v4.y;
        M[q * 4 + 2] = v4.z; M[q * 4 + 3] = v4.w;
    }
    const float* wptr = W + ((size_t)i * 10 + c) * 16;
    float w[16];
#pragma unroll
    for (int q = 0; q < 4; q++) {
        float4 v4 = *(const float4*)(wptr + q * 4);
        w[q * 4 + 0] = v4.x; w[q * 4 + 1] = v4.y;
        w[q * 4 + 2] = v4.z; w[q * 4 + 3] = v4.w;
    }
    float* op = g_v + (size_t)t * 16;
#pragma unroll
    for (int r = 0; r < 4; r++) {
        float4 o;
        o.x = M[r*4+0]*w[0] + M[r*4+1]*w[4]  + M[r*4+2]*w[8]  + M[r*4+3]*w[12];
        o.y = M[r*4+0]*w[1] + M[r*4+1]*w[5]  + M[r*4+2]*w[9]  + M[r*4+3]*w[13];
        o.z = M[r*4+0]*w[2] + M[r*4+1]*w[6]  + M[r*4+2]*w[10] + M[r*4+3]*w[14];
        o.w = M[r*4+0]*w[3] + M[r*4+1]*w[7]  + M[r*4+2]*w[11] + M[r*4+3]*w[15];
        *(float4*)(op + r * 4) = o;
    }
}

// ---------------- EM routing + final log-softmax-style output ----------------
// one CTA per batch, 320 threads = 10 warps, warp w = class c
__global__ __launch_bounds__(320) void routing_k(
    const float* __restrict__ beta_u, const float* __restrict__ beta_a,
    float* __restrict__ out)
{
    __shared__ float au_sm[800];
    __shared__ float r_sm[800 * 10];
    __shared__ float mu_sm[10][16];
    __shared__ float i2s_sm[10][16];
    __shared__ float cls_const[10];
    __shared__ float a_out_sm[10];

    int b = blockIdx.x;
    int tid = threadIdx.x;
    int c = tid >> 5;
    int lane = tid & 31;

    for (int i = tid; i < 800; i += 320) au_sm[i] = g_a[b * 800 + i];
    for (int i = tid; i < 8000; i += 320) r_sm[i] = 1.f;
    __syncthreads();

    const float* vb = g_v + (size_t)b * 800 * 160;
    const float lam_tab[3] = {0.0005f, 0.000975f, 0.00142625f};

    for (int iter = 0; iter < 3; iter++) {
        float lam = lam_tab[iter];
        // ---- phase A: per-class stats (warp c) ----
        float rs = 0.f;
        for (int i = lane; i < 800; i += 32)
            rs += r_sm[i * 10 + c] * au_sm[i];
#pragma unroll
        for (int o = 16; o; o >>= 1) rs += __shfl_xor_sync(0xffffffffu, rs, o);

        float dn = 1.f / (rs + EPS_F);
        float S0 = 0.f, S1[16], S2[16];
#pragma unroll
        for (int d = 0; d < 16; d++) { S1[d] = 0.f; S2[d] = 0.f; }

        for (int i = lane; i < 800; i += 32) {
            float wi = r_sm[i * 10 + c] * au_sm[i] * dn;
            const float4* vp = (const float4*)(vb + ((size_t)i * 10 + c) * 16);
            S0 += wi;
#pragma unroll
            for (int q = 0; q < 4; q++) {
                float4 v4 = vp[q];
                S1[q*4+0] += wi * v4.x;  S2[q*4+0] += wi * v4.x * v4.x;
                S1[q*4+1] += wi * v4.y;  S2[q*4+1] += wi * v4.y * v4.y;
                S1[q*4+2] += wi * v4.z;  S2[q*4+2] += wi * v4.z * v4.z;
                S1[q*4+3] += wi * v4.w;  S2[q*4+3] += wi * v4.w * v4.w;
            }
        }
#pragma unroll
        for (int o = 16; o; o >>= 1) {
            S0 += __shfl_xor_sync(0xffffffffu, S0, o);
#pragma unroll
            for (int d = 0; d < 16; d++) {
                S1[d] += __shfl_xor_sync(0xffffffffu, S1[d], o);
                S2[d] += __shfl_xor_sync(0xffffffffu, S2[d], o);
            }
        }
        if (lane == 0) {
            float cost = 0.f, lnpc = 0.f;
            float bu = beta_u[c];
#pragma unroll
            for (int d = 0; d < 16; d++) {
                float mu = S1[d];
                float sig = fmaxf(S2[d] - 2.f * mu * S1[d] + mu * mu * S0, 0.f) + EPS_F;
                mu_sm[c][d] = mu;
                i2s_sm[c][d] = 0.5f / sig;
                float lg = logf(sig);
                cost += bu + 0.5f * lg;
                lnpc += -0.5f * logf(sig * LN2PI_F);
            }
            float ao = 1.f / (1.f + expf(-lam * (beta_a[c] - cost * rs)));
            a_out_sm[c] = ao;
            cls_const[c] = lnpc + logf(ao);
        }
        __syncthreads();

        // ---- phase B: update r (skip on last iter) ----
        if (iter < 2) {
            for (int i = tid; i < 800; i += 320) {
                const float* vr = vb + (size_t)i * 160;
                float lp[10];
                float mx = -1e30f;
#pragma unroll
                for (int cc = 0; cc < 10; cc++) {
                    float s = 0.f;
#pragma unroll
                    for (int d = 0; d < 16; d++) {
                        float dv = vr[cc * 16 + d] - mu_sm[cc][d];
                        s += dv * dv * i2s_sm[cc][d];
                    }
                    lp[cc] = cls_const[cc] - s;
                    mx = fmaxf(mx, lp[cc]);
                }
                float sum = 0.f;
#pragma unroll
                for (int cc = 0; cc < 10; cc++) { lp[cc] = expf(lp[cc] - mx); sum += lp[cc]; }
                float inv = 1.f / sum;
#pragma unroll
                for (int cc = 0; cc < 10; cc++) r_sm[i * 10 + cc] = lp[cc] * inv;
            }
            __syncthreads();
        }
    }

    if (tid == 0) {
        float s = 0.f;
#pragma unroll
        for (int cc = 0; cc < 10; cc++) s += a_out_sm[cc];
        float ls = logf(s);
#pragma unroll
        for (int cc = 0; cc < 10; cc++)
            out[b * 10 + cc] = logf(a_out_sm[cc]) - ls;
    }
}

// ---------------- launcher ----------------
extern "C" void kernel_launch(void* const* d_in, const int* in_sizes, int n_in,
                              void* d_out, int out_size)
{
    const float* x      = (const float*)d_in[0];
    const float* w_a    = (const float*)d_in[1];
    const float* w_pose = (const float*)d_in[2];
    const float* bn_a_g = (const float*)d_in[3];
    const float* bn_a_b = (const float*)d_in[4];
    const float* bn_a_m = (const float*)d_in[5];
    const float* bn_a_v = (const float*)d_in[6];
    const float* bn_p_g = (const float*)d_in[7];
    const float* bn_p_b = (const float*)d_in[8];
    const float* bn_p_m = (const float*)d_in[9];
    const float* bn_p_v = (const float*)d_in[10];
    const float* W      = (const float*)d_in[11];
    const float* beta_u = (const float*)d_in[12];
    const float* beta_a = (const float*)d_in[13];
    float* out = (float*)d_out;

    dim3 gi(6400, 18);
    im2col_k<<<gi, 256>>>(x);

    dim3 gg(50, 9);
    conv_gemm<<<gg, 256>>>(w_a, w_pose,
                           bn_a_g, bn_a_b, bn_a_m, bn_a_v,
                           bn_p_g, bn_p_b, bn_p_m, bn_p_v);

    int vthreads = 256 * 800 * 10;
    votes_k<<<(vthreads + 255) / 256, 256>>>(W);

    routing_k<<<256, 320>>>(beta_u, beta_a, out);
}

// round 2
// speedup vs baseline: 1.0038x; 1.0038x over previous
#include <cuda_runtime.h>
#include <math.h>

// ---------------- static device scratch (no allocations allowed) ----------------
// im2col matrix: M=6400 (b*25+p), K=4608 (ci*9+ky*3+kx)
__device__ float g_col[6400 * 4608];          // 118 MB
// activations a (post BN+sigmoid): [b][i=p*32+a]  (800 per batch)
__device__ float g_a[256 * 800];
// pose (post BN): [m=b*25+p][512]
__device__ float g_pose[6400 * 512];
// votes: [b][i][c][d]  (d=16 contiguous)
__device__ float g_v[(size_t)256 * 800 * 10 * 16];  // 131 MB

#define LN2PI_F 1.8378770664093453f
#define BN_EPS_F 1e-5f
#define EPS_F 1e-12f

// ---------------- im2col ----------------
// grid: (6400, 18), block 256.  k = by*256+tid in [0,4608)
__global__ void im2col_k(const float* __restrict__ x)
{
    int k = blockIdx.y * 256 + threadIdx.x;
    int m = blockIdx.x;
    int ci = k / 9; int rem = k - ci * 9;
    int ky = rem / 3; int kx = rem - ky * 3;
    int b = m / 25; int p = m - b * 25;
    int y = p / 5;  int x0 = p - y * 5;
    int yy = y + ky - 1, xx = x0 + kx - 1;
    float v = 0.f;
    if ((unsigned)yy < 5u && (unsigned)xx < 5u)
        v = x[((b * 512 + ci) * 5 + yy) * 5 + xx];
    g_col[(size_t)m * 4608 + k] = v;
}

// ---------------- fused conv GEMM + BN (+sigmoid for a-channels) ----------------
// Out[m][n] = sum_k col[m][k] * W[n][k];  n<32 -> a conv, else pose conv (co=n-32)
// BM=128, BN=64, BK=16, 256 threads, 8x4 per-thread tile.
#define GBM 128
#define GBN 64
#define GBK 16

__global__ __launch_bounds__(256) void conv_gemm(
    const float* __restrict__ wa, const float* __restrict__ wp,
    const float* __restrict__ bag, const float* __restrict__ bab,
    const float* __restrict__ bam, const float* __restrict__ bav,
    const float* __restrict__ bpg, const float* __restrict__ bpb,
    const float* __restrict__ bpm, const float* __restrict__ bpv)
{
    __shared__ float As[GBK][GBM + 4];
    __shared__ float Bs[GBK][GBN + 4];

    int tid = threadIdx.x;
    int m0 = blockIdx.x * GBM;
    int n0 = blockIdx.y * GBN;
    int tx = tid & 15;   // 16 -> 64 cols (4 each)
    int ty = tid >> 4;   // 16 -> 128 rows (8 each)

    float acc[8][4];
#pragma unroll
    for (int i = 0; i < 8; i++)
#pragma unroll
        for (int j = 0; j < 4; j++) acc[i][j] = 0.f;

    int lrow  = tid >> 2;        // 0..63
    int lcol4 = (tid & 3) * 4;   // 0,4,8,12

    for (int k0 = 0; k0 < 4608; k0 += GBK) {
        // A tile: 128 x 16
#pragma unroll
        for (int it = 0; it < 2; it++) {
            int r = lrow + it * 64;
            float4 va = *(const float4*)&g_col[(size_t)(m0 + r) * 4608 + k0 + lcol4];
            As[lcol4 + 0][r] = va.x;
            As[lcol4 + 1][r] = va.y;
            As[lcol4 + 2][r] = va.z;
            As[lcol4 + 3][r] = va.w;
        }
        // B tile: 64 x 16
        {
            int n = n0 + lrow;
            float4 vb = make_float4(0.f, 0.f, 0.f, 0.f);
            if (n < 544) {
                const float* brow = (n < 32) ? (wa + (size_t)n * 4608)
                                             : (wp + (size_t)(n - 32) * 4608);
                vb = *(const float4*)&brow[k0 + lcol4];
            }
            Bs[lcol4 + 0][lrow] = vb.x;
            Bs[lcol4 + 1][lrow] = vb.y;
            Bs[lcol4 + 2][lrow] = vb.z;
            Bs[lcol4 + 3][lrow] = vb.w;
        }
        __syncthreads();

#pragma unroll
        for (int kk = 0; kk < GBK; kk++) {
            float a[8], bvals[4];
#pragma unroll
            for (int i = 0; i < 8; i++) a[i] = As[kk][ty * 8 + i];
#pragma unroll
            for (int j = 0; j < 4; j++) bvals[j] = Bs[kk][tx * 4 + j];
#pragma unroll
            for (int i = 0; i < 8; i++)
#pragma unroll
                for (int j = 0; j < 4; j++)
                    acc[i][j] = fmaf(a[i], bvals[j], acc[i][j]);
        }
        __syncthreads();
    }

    // epilogue: BN (+sigmoid for a), scatter to g_a / g_pose
#pragma unroll
    for (int i = 0; i < 8; i++) {
        int m = m0 + ty * 8 + i;           // always < 6400 (50 exact tiles)
        int b = m / 25, p = m - b * 25;
#pragma unroll
        for (int j = 0; j < 4; j++) {
            int n = n0 + tx * 4 + j;
            if (n >= 544) continue;
            float val = acc[i][j];
            if (n < 32) {
                float sc = bag[n] * rsqrtf(bav[n] + BN_EPS_F);
                val = (val - bam[n]) * sc + bab[n];
                g_a[b * 800 + p * 32 + n] = 1.f / (1.f + expf(-val));
            } else {
                int co = n - 32;
                float sc = bpg[co] * rsqrtf(bpv[co] + BN_EPS_F);
                val = (val - bpm[co]) * sc + bpb[co];
                g_pose[(size_t)m * 512 + co] = val;
            }
        }
    }
}

// ---------------- votes: v[b][i][c][r*4+s] = M_i(4x4) @ W[i][c](4x4) ----------------
// one thread per (b,i,c); t = (b*800+i)*10+c
__global__ __launch_bounds__(256) void votes_k(const float* __restrict__ W)
{
    int t = blockIdx.x * blockDim.x + threadIdx.x;
    if (t >= 256 * 800 * 10) return;
    int c  = t % 10;
    int bi = t / 10;
    int i  = bi % 800;
    int b  = bi / 800;
    int a  = i & 31, p = i >> 5;

    const float* mp = g_pose + (size_t)(b * 25 + p) * 512 + a * 16;
    float M[16];
#pragma unroll
    for (int q = 0; q < 4; q++) {
        float4 v4 = *(const float4*)(mp + q * 4);
        M[q * 4 + 0] = v4.x; M[q * 4 + 1] = v4.y;
        M[q * 4 + 2] = v4.z; M[q * 4 + 3] = v4.w;
    }
    const float* wptr = W + ((size_t)i * 10 + c) * 16;
    float w[16];
#pragma unroll
    for (int q = 0; q < 4; q++) {
        float4 v4 = *(const float4*)(wptr + q * 4);
        w[q * 4 + 0] = v4.x; w[q * 4 + 1] = v4.y;
        w[q * 4 + 2] = v4.z; w[q * 4 + 3] = v4.w;
    }
    float* op = g_v + (size_t)t * 16;
#pragma unroll
    for (int r = 0; r < 4; r++) {
        float4 o;
        o.x = M[r*4+0]*w[0] + M[r*4+1]*w[4]  + M[r*4+2]*w[8]  + M[r*4+3]*w[12];
        o.y = M[r*4+0]*w[1] + M[r*4+1]*w[5]  + M[r*4+2]*w[9]  + M[r*4+3]*w[13];
        o.z = M[r*4+0]*w[2] + M[r*4+1]*w[6]  + M[r*4+2]*w[10] + M[r*4+3]*w[14];
        o.w = M[r*4+0]*w[3] + M[r*4+1]*w[7]  + M[r*4+2]*w[11] + M[r*4+3]*w[15];
        *(float4*)(op + r * 4) = o;
    }
}

// ---------------- EM routing + final log-softmax-style output ----------------
// one CTA per batch, 320 threads = 10 warps, warp w = class c
__global__ __launch_bounds__(320) void routing_k(
    const float* __restrict__ beta_u, const float* __restrict__ beta_a,
    float* __restrict__ out)
{
    __shared__ float au_sm[800];
    __shared__ float r_sm[800 * 10];
    __shared__ float mu_sm[10][16];
    __shared__ float i2s_sm[10][16];
    __shared__ float cls_const[10];
    __shared__ float a_out_sm[10];

    int b = blockIdx.x;
    int tid = threadIdx.x;
    int c = tid >> 5;
    int lane = tid & 31;

    for (int i = tid; i < 800; i += 320) au_sm[i] = g_a[b * 800 + i];
    for (int i = tid; i < 8000; i += 320) r_sm[i] = 1.f;
    __syncthreads();

    const float* vb = g_v + (size_t)b * 800 * 160;
    const float lam_tab[3] = {0.0005f, 0.000975f, 0.00142625f};

    for (int iter = 0; iter < 3; iter++) {
        float lam = lam_tab[iter];
        // ---- phase A: per-class stats (warp c) ----
        float rs = 0.f;
        for (int i = lane; i < 800; i += 32)
            rs += r_sm[i * 10 + c] * au_sm[i];
#pragma unroll
        for (int o = 16; o; o >>= 1) rs += __shfl_xor_sync(0xffffffffu, rs, o);

        float dn = 1.f / (rs + EPS_F);
        float S0 = 0.f, S1[16], S2[16];
#pragma unroll
        for (int d = 0; d < 16; d++) { S1[d] = 0.f; S2[d] = 0.f; }

        for (int i = lane; i < 800; i += 32) {
            float wi = r_sm[i * 10 + c] * au_sm[i] * dn;
            const float4* vp = (const float4*)(vb + ((size_t)i * 10 + c) * 16);
            S0 += wi;
#pragma unroll
            for (int q = 0; q < 4; q++) {
                float4 v4 = vp[q];
                S1[q*4+0] += wi * v4.x;  S2[q*4+0] += wi * v4.x * v4.x;
                S1[q*4+1] += wi * v4.y;  S2[q*4+1] += wi * v4.y * v4.y;
                S1[q*4+2] += wi * v4.z;  S2[q*4+2] += wi * v4.z * v4.z;
                S1[q*4+3] += wi * v4.w;  S2[q*4+3] += wi * v4.w * v4.w;
            }
        }
#pragma unroll
        for (int o = 16; o; o >>= 1) {
            S0 += __shfl_xor_sync(0xffffffffu, S0, o);
#pragma unroll
            for (int d = 0; d < 16; d++) {
                S1[d] += __shfl_xor_sync(0xffffffffu, S1[d], o);
                S2[d] += __shfl_xor_sync(0xffffffffu, S2[d], o);
            }
        }
        if (lane == 0) {
            float cost = 0.f, lnpc = 0.f;
            float bu = beta_u[c];
#pragma unroll
            for (int d = 0; d < 16; d++) {
                float mu = S1[d];
                float sig = fmaxf(S2[d] - 2.f * mu * S1[d] + mu * mu * S0, 0.f) + EPS_F;
                mu_sm[c][d] = mu;
                i2s_sm[c][d] = 0.5f / sig;
                float lg = logf(sig);
                cost += bu + 0.5f * lg;
                lnpc += -0.5f * logf(sig * LN2PI_F);
            }
            float ao = 1.f / (1.f + expf(-lam * (beta_a[c] - cost * rs)));
            a_out_sm[c] = ao;
            cls_const[c] = lnpc + logf(ao);
        }
        __syncthreads();

        // ---- phase B: update r (skip on last iter) ----
        if (iter < 2) {
            for (int i = tid; i < 800; i += 320) {
                const float* vr = vb + (size_t)i * 160;
                float lp[10];
                float mx = -1e30f;
#pragma unroll
                for (int cc = 0; cc < 10; cc++) {
                    float s = 0.f;
#pragma unroll
                    for (int d = 0; d < 16; d++) {
                        float dv = vr[cc * 16 + d] - mu_sm[cc][d];
                        s += dv * dv * i2s_sm[cc][d];
                    }
                    lp[cc] = cls_const[cc] - s;
                    mx = fmaxf(mx, lp[cc]);
                }
                float sum = 0.f;
#pragma unroll
                for (int cc = 0; cc < 10; cc++) { lp[cc] = expf(lp[cc] - mx); sum += lp[cc]; }
                float inv = 1.f / sum;
#pragma unroll
                for (int cc = 0; cc < 10; cc++) r_sm[i * 10 + cc] = lp[cc] * inv;
            }
            __syncthreads();
        }
    }

    if (tid == 0) {
        float s = 0.f;
#pragma unroll
        for (int cc = 0; cc < 10; cc++) s += a_out_sm[cc];
        float ls = logf(s);
#pragma unroll
        for (int cc = 0; cc < 10; cc++)
            out[b * 10 + cc] = logf(a_out_sm[cc]) - ls;
    }
}

// ---------------- launcher ----------------
extern "C" void kernel_launch(void* const* d_in, const int* in_sizes, int n_in,
                              void* d_out, int out_size)
{
    const float* x      = (const float*)d_in[0];
    const float* w_a    = (const float*)d_in[1];
    const float* w_pose = (const float*)d_in[2];
    const float* bn_a_g = (const float*)d_in[3];
    const float* bn_a_b = (const float*)d_in[4];
    const float* bn_a_m = (const float*)d_in[5];
    const float* bn_a_v = (const float*)d_in[6];
    const float* bn_p_g = (const float*)d_in[7];
    const float* bn_p_b = (const float*)d_in[8];
    const float* bn_p_m = (const float*)d_in[9];
    const float* bn_p_v = (const float*)d_in[10];
    const float* W      = (const float*)d_in[11];
    const float* beta_u = (const float*)d_in[12];
    const float* beta_a = (const float*)d_in[13];
    float* out = (float*)d_out;

    dim3 gi(6400, 18);
    im2col_k<<<gi, 256>>>(x);

    dim3 gg(50, 9);
    conv_gemm<<<gg, 256>>>(w_a, w_pose,
                           bn_a_g, bn_a_b, bn_a_m, bn_a_v,
                           bn_p_g, bn_p_b, bn_p_m, bn_p_v);

    int vthreads = 256 * 800 * 10;
    votes_k<<<(vthreads + 255) / 256, 256>>>(W);

    routing_k<<<256, 320>>>(beta_u, beta_a, out);
}

// round 3
// speedup vs baseline: 1.7351x; 1.7285x over previous
#include <cuda_runtime.h>
#include <math.h>
#include <stdint.h>

// ---------------- static device scratch ----------------
// im2col matrix (tf32-rounded fp32): M=6400 (b*25+p), K=4608 (ci*9+ky*3+kx)
__device__ float g_col[6400 * 4608];          // 118 MB
// activations a (post BN+sigmoid): [b][i=p*32+a]
__device__ float g_a[256 * 800];
// pose (post BN): [m=b*25+p][512]
__device__ float g_pose[6400 * 512];

#define LN2PI_F 1.8378770664093453f
#define BN_EPS_F 1e-5f
#define EPS_F 1e-12f

__device__ __forceinline__ uint32_t f2tf32(float f) {
    uint32_t r;
    asm("cvt.rna.tf32.f32 %0, %1;" : "=r"(r) : "f"(f));
    return r;
}

__device__ __forceinline__ void mma_tf32(
    float& c0, float& c1, float& c2, float& c3,
    uint32_t a0, uint32_t a1, uint32_t a2, uint32_t a3,
    uint32_t b0, uint32_t b1)
{
    asm volatile(
        "mma.sync.aligned.m16n8k8.row.col.f32.tf32.tf32.f32 "
        "{%0,%1,%2,%3}, {%4,%5,%6,%7}, {%8,%9}, {%0,%1,%2,%3};"
        : "+f"(c0), "+f"(c1), "+f"(c2), "+f"(c3)
        : "r"(a0), "r"(a1), "r"(a2), "r"(a3), "r"(b0), "r"(b1));
}

// ---------------- im2col (writes tf32-rounded values) ----------------
__global__ void im2col_k(const float* __restrict__ x)
{
    int k = blockIdx.y * 256 + threadIdx.x;
    int m = blockIdx.x;
    int ci = k / 9; int rem = k - ci * 9;
    int ky = rem / 3; int kx = rem - ky * 3;
    int b = m / 25; int p = m - b * 25;
    int y = p / 5;  int x0 = p - y * 5;
    int yy = y + ky - 1, xx = x0 + kx - 1;
    float v = 0.f;
    if ((unsigned)yy < 5u && (unsigned)xx < 5u)
        v = x[((b * 512 + ci) * 5 + yy) * 5 + xx];
    g_col[(size_t)m * 4608 + k] = __uint_as_float(f2tf32(v));
}

// ---------------- tf32 tensor-core conv GEMM + BN epilogue ----------------
// Out[m][n] = sum_k col[m][k] * W[n][k];  n<32 -> a conv (sigmoid), else pose
// BM=128, BN=128, BK=32; 256 threads = 8 warps as 4(M) x 2(N); warp tile 32x64.
#define ASTRIDE 36
#define BSTRIDE 136

__global__ __launch_bounds__(256) void conv_gemm_tc(
    const float* __restrict__ wa, const float* __restrict__ wp,
    const float* __restrict__ bag, const float* __restrict__ bab,
    const float* __restrict__ bam, const float* __restrict__ bav,
    const float* __restrict__ bpg, const float* __restrict__ bpb,
    const float* __restrict__ bpm, const float* __restrict__ bpv)
{
    __shared__ float As[128 * ASTRIDE];   // [row][k], stride 36
    __shared__ float Bs[32 * BSTRIDE];    // [k][n],  stride 136

    int tid = threadIdx.x;
    int m0 = blockIdx.x * 128;
    int n0 = blockIdx.y * 128;

    int warp = tid >> 5;
    int lane = tid & 31;
    int g = lane >> 2;      // groupID 0..7
    int q = lane & 3;       // thread in group 0..3
    int wm = warp & 3;      // 0..3  (M)
    int wn = warp >> 2;     // 0..1  (N)

    // A-tile load indices
    int rowA = tid >> 1;
    int halfA = tid & 1;
    // B-tile load indices
    int nl = tid & 127;
    int kq0 = tid >> 7;     // 0..1

    float acc[2][8][4];
#pragma unroll
    for (int mt = 0; mt < 2; mt++)
#pragma unroll
        for (int nt = 0; nt < 8; nt++)
#pragma unroll
            for (int e = 0; e < 4; e++) acc[mt][nt][e] = 0.f;

    int nglob = n0 + nl;
    const float* brow = nullptr;
    if (nglob < 32)       brow = wa + (size_t)nglob * 4608;
    else if (nglob < 544) brow = wp + (size_t)(nglob - 32) * 4608;

    for (int k0 = 0; k0 < 4608; k0 += 32) {
        // load A (already tf32-rounded in g_col)
#pragma unroll
        for (int j = 0; j < 4; j++) {
            int col = halfA * 16 + j * 4;
            float4 v = *(const float4*)&g_col[(size_t)(m0 + rowA) * 4608 + k0 + col];
            *(float4*)&As[rowA * ASTRIDE + col] = v;
        }
        // load B, convert to tf32, store transposed [k][n]
#pragma unroll
        for (int kk = kq0; kk < 8; kk += 2) {
            float4 v = make_float4(0.f, 0.f, 0.f, 0.f);
            if (brow) v = *(const float4*)&brow[k0 + kk * 4];
            Bs[(kk * 4 + 0) * BSTRIDE + nl] = __uint_as_float(f2tf32(v.x));
            Bs[(kk * 4 + 1) * BSTRIDE + nl] = __uint_as_float(f2tf32(v.y));
            Bs[(kk * 4 + 2) * BSTRIDE + nl] = __uint_as_float(f2tf32(v.z));
            Bs[(kk * 4 + 3) * BSTRIDE + nl] = __uint_as_float(f2tf32(v.w));
        }
        __syncthreads();

#pragma unroll
        for (int ks = 0; ks < 4; ks++) {
            uint32_t af[2][4];
#pragma unroll
            for (int mt = 0; mt < 2; mt++) {
                int ra = (wm * 32 + mt * 16 + g) * ASTRIDE + ks * 8 + q;
                af[mt][0] = __float_as_uint(As[ra]);
                af[mt][1] = __float_as_uint(As[ra + 8 * ASTRIDE]);
                af[mt][2] = __float_as_uint(As[ra + 4]);
                af[mt][3] = __float_as_uint(As[ra + 8 * ASTRIDE + 4]);
            }
#pragma unroll
            for (int nt = 0; nt < 8; nt++) {
                int rb = (ks * 8 + q) * BSTRIDE + wn * 64 + nt * 8 + g;
                uint32_t b0 = __float_as_uint(Bs[rb]);
                uint32_t b1 = __float_as_uint(Bs[rb + 4 * BSTRIDE]);
#pragma unroll
                for (int mt = 0; mt < 2; mt++)
                    mma_tf32(acc[mt][nt][0], acc[mt][nt][1], acc[mt][nt][2], acc[mt][nt][3],
                             af[mt][0], af[mt][1], af[mt][2], af[mt][3], b0, b1);
            }
        }
        __syncthreads();
    }

    // epilogue: BN (+sigmoid for a-channels)
#pragma unroll
    for (int mt = 0; mt < 2; mt++) {
#pragma unroll
        for (int nt = 0; nt < 8; nt++) {
#pragma unroll
            for (int e = 0; e < 4; e++) {
                int m = m0 + wm * 32 + mt * 16 + g + ((e >= 2) ? 8 : 0);
                int n = n0 + wn * 64 + nt * 8 + 2 * q + (e & 1);
                if (n >= 544) continue;
                int b = m / 25, p = m - b * 25;
                float val = acc[mt][nt][e];
                if (n < 32) {
                    float sc = bag[n] * rsqrtf(bav[n] + BN_EPS_F);
                    val = (val - bam[n]) * sc + bab[n];
                    g_a[b * 800 + p * 32 + n] = 1.f / (1.f + expf(-val));
                } else {
                    int co = n - 32;
                    float sc = bpg[co] * rsqrtf(bpv[co] + BN_EPS_F);
                    val = (val - bpm[co]) * sc + bpb[co];
                    g_pose[(size_t)m * 512 + co] = val;
                }
            }
        }
    }
}

// ---------------- EM routing with on-the-fly vote recompute ----------------
// one CTA per batch, 640 threads = 20 warps; class c = warp>>1, half h = warp&1.
// Votes v[i][c] = M_i (4x4, row-major) @ W[i][c] (4x4, row-major), recomputed.
__global__ __launch_bounds__(640) void routing_k(
    const float* __restrict__ Wg,
    const float* __restrict__ beta_u, const float* __restrict__ beta_a,
    float* __restrict__ out)
{
    extern __shared__ float sm[];
    float* pose_T = sm;             // [16][800]
    float* r_sm   = sm + 12800;     // [10][800]
    float* au_sm  = r_sm + 8000;    // [800]
    float* part   = au_sm + 800;    // [20][33]
    float* mu_sm  = part + 660;     // [10][16]
    float* i2s_sm = mu_sm + 160;    // [10][16]
    float* ccst   = i2s_sm + 160;   // [10]
    float* aout   = ccst + 10;      // [10]

    int b = blockIdx.x;
    int tid = threadIdx.x;
    int w = tid >> 5;
    int lane = tid & 31;
    int c = w >> 1;
    int h = w & 1;

    // load pose transposed: pose_T[d][i] = pose of capsule i, dim d
    for (int idx = tid; idx < 12800; idx += 640) {
        int i = idx >> 4, d = idx & 15;
        pose_T[d * 800 + i] =
            g_pose[(size_t)(b * 25 + (i >> 5)) * 512 + (i & 31) * 16 + d];
    }
    for (int i = tid; i < 800; i += 640) au_sm[i] = g_a[b * 800 + i];
    for (int idx = tid; idx < 8000; idx += 640) r_sm[idx] = 1.f;
    __syncthreads();

    const float lam_tab[3] = {0.0005f, 0.000975f, 0.00142625f};

    for (int iter = 0; iter < 3; iter++) {
        // ---- phase A: per-class weighted stats (warp (c,h)) ----
        float T0 = 0.f, T1[16], T2[16];
#pragma unroll
        for (int d = 0; d < 16; d++) { T1[d] = 0.f; T2[d] = 0.f; }

        for (int i = h * 400 + lane; i < h * 400 + 400; i += 32) {
            float rw = r_sm[c * 800 + i] * au_sm[i];
            const float4* W4 = (const float4*)(Wg + ((size_t)i * 10 + c) * 16);
            float4 w0 = W4[0], w1 = W4[1], w2 = W4[2], w3 = W4[3];
            T0 += rw;
#pragma unroll
            for (int rr = 0; rr < 4; rr++) {
                float m0 = pose_T[(rr * 4 + 0) * 800 + i];
                float m1 = pose_T[(rr * 4 + 1) * 800 + i];
                float m2 = pose_T[(rr * 4 + 2) * 800 + i];
                float m3 = pose_T[(rr * 4 + 3) * 800 + i];
                float v0 = m0 * w0.x + m1 * w1.x + m2 * w2.x + m3 * w3.x;
                float v1 = m0 * w0.y + m1 * w1.y + m2 * w2.y + m3 * w3.y;
                float v2 = m0 * w0.z + m1 * w1.z + m2 * w2.z + m3 * w3.z;
                float v3 = m0 * w0.w + m1 * w1.w + m2 * w2.w + m3 * w3.w;
                T1[rr * 4 + 0] += rw * v0;  T2[rr * 4 + 0] += rw * v0 * v0;
                T1[rr * 4 + 1] += rw * v1;  T2[rr * 4 + 1] += rw * v1 * v1;
                T1[rr * 4 + 2] += rw * v2;  T2[rr * 4 + 2] += rw * v2 * v2;
                T1[rr * 4 + 3] += rw * v3;  T2[rr * 4 + 3] += rw * v3 * v3;
            }
        }
#pragma unroll
        for (int o = 16; o; o >>= 1) {
            T0 += __shfl_xor_sync(0xffffffffu, T0, o);
#pragma unroll
            for (int d = 0; d < 16; d++) {
                T1[d] += __shfl_xor_sync(0xffffffffu, T1[d], o);
                T2[d] += __shfl_xor_sync(0xffffffffu, T2[d], o);
            }
        }
        if (lane == 0) {
            float* pp = part + w * 33;
            pp[0] = T0;
#pragma unroll
            for (int d = 0; d < 16; d++) { pp[1 + d] = T1[d]; pp[17 + d] = T2[d]; }
        }
        __syncthreads();

        if (tid < 10) {
            int cc = tid;
            const float* pa = part + (2 * cc) * 33;
            const float* pb = part + (2 * cc + 1) * 33;
            float t0 = pa[0] + pb[0];
            float dn = 1.f / (t0 + EPS_F);
            float t = dn * t0;
            float bu = beta_u[cc];
            float cost = 0.f, lnp = 0.f;
#pragma unroll
            for (int d = 0; d < 16; d++) {
                float t1 = pa[1 + d] + pb[1 + d];
                float t2 = pa[17 + d] + pb[17 + d];
                float mu = dn * t1;
                float sig = fmaxf(dn * t2 - mu * mu * (2.f - t), 0.f) + EPS_F;
                mu_sm[cc * 16 + d] = mu;
                i2s_sm[cc * 16 + d] = 0.5f / sig;
                float lg = logf(sig);
                cost += bu + 0.5f * lg;
                lnp += -0.5f * logf(sig * LN2PI_F);
            }
            float lam = lam_tab[iter];
            float ao = 1.f / (1.f + expf(-lam * (beta_a[cc] - cost * t0)));
            aout[cc] = ao;
            ccst[cc] = lnp + logf(ao);
        }
        __syncthreads();

        // ---- phase B: update r (skip on last iter) ----
        if (iter < 2) {
            for (int i = tid; i < 800; i += 640) {
                float m[16];
#pragma unroll
                for (int d = 0; d < 16; d++) m[d] = pose_T[d * 800 + i];
                const float* Wr = Wg + (size_t)i * 160;
                float lp[10];
                float mx = -1e30f;
#pragma unroll
                for (int cc = 0; cc < 10; cc++) {
                    const float4* W4 = (const float4*)(Wr + cc * 16);
                    float4 w0 = W4[0], w1 = W4[1], w2 = W4[2], w3 = W4[3];
                    float s = 0.f;
#pragma unroll
                    for (int rr = 0; rr < 4; rr++) {
                        float m0 = m[rr * 4 + 0], m1 = m[rr * 4 + 1];
                        float m2 = m[rr * 4 + 2], m3 = m[rr * 4 + 3];
                        float v0 = m0 * w0.x + m1 * w1.x + m2 * w2.x + m3 * w3.x;
                        float v1 = m0 * w0.y + m1 * w1.y + m2 * w2.y + m3 * w3.y;
                        float v2 = m0 * w0.z + m1 * w1.z + m2 * w2.z + m3 * w3.z;
                        float v3 = m0 * w0.w + m1 * w1.w + m2 * w2.w + m3 * w3.w;
                        float d0 = v0 - mu_sm[cc * 16 + rr * 4 + 0];
                        float d1 = v1 - mu_sm[cc * 16 + rr * 4 + 1];
                        float d2 = v2 - mu_sm[cc * 16 + rr * 4 + 2];
                        float d3 = v3 - mu_sm[cc * 16 + rr * 4 + 3];
                        s += d0 * d0 * i2s_sm[cc * 16 + rr * 4 + 0];
                        s += d1 * d1 * i2s_sm[cc * 16 + rr * 4 + 1];
                        s += d2 * d2 * i2s_sm[cc * 16 + rr * 4 + 2];
                        s += d3 * d3 * i2s_sm[cc * 16 + rr * 4 + 3];
                    }
                    lp[cc] = ccst[cc] - s;
                    mx = fmaxf(mx, lp[cc]);
                }
                float sum = 0.f;
#pragma unroll
                for (int cc = 0; cc < 10; cc++) { lp[cc] = expf(lp[cc] - mx); sum += lp[cc]; }
                float inv = 1.f / sum;
#pragma unroll
                for (int cc = 0; cc < 10; cc++) r_sm[cc * 800 + i] = lp[cc] * inv;
            }
            __syncthreads();
        }
    }

    if (tid == 0) {
        float s = 0.f;
#pragma unroll
        for (int cc = 0; cc < 10; cc++) s += aout[cc];
        float ls = logf(s);
#pragma unroll
        for (int cc = 0; cc < 10; cc++)
            out[b * 10 + cc] = logf(aout[cc]) - ls;
    }
}

// ---------------- launcher ----------------
extern "C" void kernel_launch(void* const* d_in, const int* in_sizes, int n_in,
                              void* d_out, int out_size)
{
    const float* x      = (const float*)d_in[0];
    const float* w_a    = (const float*)d_in[1];
    const float* w_pose = (const float*)d_in[2];
    const float* bn_a_g = (const float*)d_in[3];
    const float* bn_a_b = (const float*)d_in[4];
    const float* bn_a_m = (const float*)d_in[5];
    const float* bn_a_v = (const float*)d_in[6];
    const float* bn_p_g = (const float*)d_in[7];
    const float* bn_p_b = (const float*)d_in[8];
    const float* bn_p_m = (const float*)d_in[9];
    const float* bn_p_v = (const float*)d_in[10];
    const float* W      = (const float*)d_in[11];
    const float* beta_u = (const float*)d_in[12];
    const float* beta_a = (const float*)d_in[13];
    float* out = (float*)d_out;

    cudaFuncSetAttribute(routing_k, cudaFuncAttributeMaxDynamicSharedMemorySize,
                         92 * 1024);

    dim3 gi(6400, 18);
    im2col_k<<<gi, 256>>>(x);

    dim3 gg(50, 5);
    conv_gemm_tc<<<gg, 256>>>(w_a, w_pose,
                              bn_a_g, bn_a_b, bn_a_m, bn_a_v,
                              bn_p_g, bn_p_b, bn_p_m, bn_p_v);

    routing_k<<<256, 640, 92 * 1024>>>(W, beta_u, beta_a, out);
}

// round 5
// speedup vs baseline: 3.2434x; 1.8693x over previous
#include <cuda_runtime.h>
#include <cuda_bf16.h>
#include <math.h>
#include <stdint.h>

// ---------------- static device scratch ----------------
__device__ __nv_bfloat16 g_col[(size_t)6400 * 4608];   // im2col bf16, 59 MB
__device__ __nv_bfloat16 g_wb[(size_t)544 * 4608];     // packed weights bf16
__device__ float g_a[256 * 800];                        // post BN+sigmoid
__device__ float g_pose[(size_t)6400 * 512];            // post BN

#define LN2PI_F 1.8378770664093453f
#define BN_EPS_F 1e-5f
#define EPS_F 1e-12f

__device__ __forceinline__ uint32_t smem_u32(const void* p) {
    uint32_t a;
    asm("{ .reg .u64 t; cvta.to.shared.u64 t, %1; cvt.u32.u64 %0, t; }"
        : "=r"(a) : "l"(p));
    return a;
}
__device__ __forceinline__ void cp_async16(uint32_t dst, const void* src) {
    asm volatile("cp.async.cg.shared.global [%0], [%1], 16;"
                 :: "r"(dst), "l"(src) : "memory");
}
#define CP_COMMIT() asm volatile("cp.async.commit_group;" ::: "memory")
#define CP_WAIT0()  asm volatile("cp.async.wait_group 0;" ::: "memory")

__device__ __forceinline__ void mma_bf16(
    float& c0, float& c1, float& c2, float& c3,
    uint32_t a0, uint32_t a1, uint32_t a2, uint32_t a3,
    uint32_t b0, uint32_t b1)
{
    asm volatile(
        "mma.sync.aligned.m16n8k16.row.col.f32.bf16.bf16.f32 "
        "{%0,%1,%2,%3}, {%4,%5,%6,%7}, {%8,%9}, {%0,%1,%2,%3};"
        : "+f"(c0), "+f"(c1), "+f"(c2), "+f"(c3)
        : "r"(a0), "r"(a1), "r"(a2), "r"(a3), "r"(b0), "r"(b1));
}

// ---------------- im2col (bf16 output) ----------------
__global__ void im2col_k(const float* __restrict__ x)
{
    int t = blockIdx.y * 256 + threadIdx.x;      // 0..2303
    int m = blockIdx.x;
    int b = m / 25, p = m - b * 25;
    int y = p / 5, x0 = p - y * 5;
    int k0 = t * 2;
    float v[2];
#pragma unroll
    for (int j = 0; j < 2; j++) {
        int k = k0 + j;
        int ci = k / 9; int rem = k - ci * 9;
        int ky = rem / 3, kx = rem - ky * 3;
        int yy = y + ky - 1, xx = x0 + kx - 1;
        v[j] = 0.f;
        if ((unsigned)yy < 5u && (unsigned)xx < 5u)
            v[j] = x[((b * 512 + ci) * 5 + yy) * 5 + xx];
    }
    __nv_bfloat162 o;
    o.x = __float2bfloat16(v[0]);
    o.y = __float2bfloat16(v[1]);
    *(__nv_bfloat162*)&g_col[(size_t)m * 4608 + k0] = o;
}

// ---------------- weight pack: [544][4608] bf16 ----------------
__global__ void wpack_k(const float* __restrict__ wa, const float* __restrict__ wp)
{
    int idx = blockIdx.x * 256 + threadIdx.x;
    if (idx >= 544 * 4608 / 4) return;
    int e = idx * 4;
    int n = e / 4608, k = e - n * 4608;
    const float* src = (n < 32) ? (wa + (size_t)n * 4608 + k)
                                : (wp + (size_t)(n - 32) * 4608 + k);
    float4 v = *(const float4*)src;
    __nv_bfloat162 o0, o1;
    o0.x = __float2bfloat16(v.x); o0.y = __float2bfloat16(v.y);
    o1.x = __float2bfloat16(v.z); o1.y = __float2bfloat16(v.w);
    *(__nv_bfloat162*)&g_wb[(size_t)n * 4608 + k]     = o0;
    *(__nv_bfloat162*)&g_wb[(size_t)n * 4608 + k + 2] = o1;
}

// ---------------- bf16 mma.sync GEMM + BN epilogue ----------------
// D[m][n] = sum_k col[m][k] * W[n][k]
// BM=128, BN=128, BK=64, 2-stage cp.async double buffer.
// 8 warps = 4(M) x 2(N); warp tile 32x64; mma m16n8k16 -> 2x8 per kstep, 4 ksteps.
#define BK 64
#define TSTRIDE 72            // bf16 elems per row in smem (64 + 8 pad; 144B, 16B aligned)
#define ASTG (128 * TSTRIDE)  // 9216 elems per stage
#define NCHUNK 72

__global__ __launch_bounds__(256) void gemm_bf16(
    const float* __restrict__ bag, const float* __restrict__ bab,
    const float* __restrict__ bam, const float* __restrict__ bav,
    const float* __restrict__ bpg, const float* __restrict__ bpb,
    const float* __restrict__ bpm, const float* __restrict__ bpv)
{
    extern __shared__ __nv_bfloat16 sm[];
    // layout: A0 [0,9216) A1 [9216,18432) B0 [18432,27648) B1 [27648,36864)
    uint32_t sb = smem_u32(sm);

    int tid = threadIdx.x;
    int warp = tid >> 5, lane = tid & 31;
    int g = lane >> 2, q = lane & 3;
    int wm = warp & 3, wn = warp >> 2;

    int m0 = blockIdx.x * 128;
    int n0 = blockIdx.y * 128;

    // loader indices: 1024 uint4 per tile (A), 256 threads -> 4 each
    int lrow = tid >> 1;              // unused path replaced below
    (void)lrow;

    float acc[2][8][4];
#pragma unroll
    for (int mt = 0; mt < 2; mt++)
#pragma unroll
        for (int nt = 0; nt < 8; nt++)
#pragma unroll
            for (int e = 0; e < 4; e++) acc[mt][nt][e] = 0.f;

    // per-thread load descriptors (4 A rows + 4 B rows, fixed across chunks)
    int arow[4], aq[4], brow[4], bq[4];
    bool bval[4];
#pragma unroll
    for (int i = 0; i < 4; i++) {
        int u = i * 256 + tid;
        arow[i] = u >> 3; aq[i] = u & 7;
        brow[i] = u >> 3; bq[i] = u & 7;
        bval[i] = (n0 + brow[i]) < 544;
    }

    auto load_chunk = [&](int s, int k0) {
        uint32_t abase = sb + (uint32_t)(s * ASTG) * 2;
        uint32_t bbase = sb + (uint32_t)((2 + s) * ASTG) * 2;
#pragma unroll
        for (int i = 0; i < 4; i++) {
            const __nv_bfloat16* src =
                &g_col[(size_t)(m0 + arow[i]) * 4608 + k0 + aq[i] * 8];
            cp_async16(abase + arow[i] * (TSTRIDE * 2) + aq[i] * 16, src);
        }
#pragma unroll
        for (int i = 0; i < 4; i++) {
            uint32_t dst = bbase + brow[i] * (TSTRIDE * 2) + bq[i] * 16;
            if (bval[i]) {
                const __nv_bfloat16* src =
                    &g_wb[(size_t)(n0 + brow[i]) * 4608 + k0 + bq[i] * 8];
                cp_async16(dst, src);
            } else {
                *(uint4*)(((char*)sm) + (dst - sb)) = make_uint4(0, 0, 0, 0);
            }
        }
        CP_COMMIT();
    };

    load_chunk(0, 0);
    CP_WAIT0();
    __syncthreads();

    for (int c = 0; c < NCHUNK; c++) {
        int s = c & 1;
        if (c + 1 < NCHUNK) load_chunk(s ^ 1, (c + 1) * BK);

        const __nv_bfloat16* As = sm + s * ASTG;
        const __nv_bfloat16* Bs = sm + (2 + s) * ASTG;

#pragma unroll
        for (int ks = 0; ks < 4; ks++) {
            uint32_t af[2][4];
#pragma unroll
            for (int mt = 0; mt < 2; mt++) {
                int rb = wm * 32 + mt * 16 + g;
                const __nv_bfloat16* p0 = As + rb * TSTRIDE + ks * 16 + 2 * q;
                af[mt][0] = *(const uint32_t*)p0;
                af[mt][1] = *(const uint32_t*)(p0 + 8 * TSTRIDE);
                af[mt][2] = *(const uint32_t*)(p0 + 8);
                af[mt][3] = *(const uint32_t*)(p0 + 8 * TSTRIDE + 8);
            }
#pragma unroll
            for (int nt = 0; nt < 8; nt++) {
                int nl = wn * 64 + nt * 8 + g;
                const __nv_bfloat16* pb = Bs + nl * TSTRIDE + ks * 16 + 2 * q;
                uint32_t b0 = *(const uint32_t*)pb;
                uint32_t b1 = *(const uint32_t*)(pb + 8);
#pragma unroll
                for (int mt = 0; mt < 2; mt++)
                    mma_bf16(acc[mt][nt][0], acc[mt][nt][1],
                             acc[mt][nt][2], acc[mt][nt][3],
                             af[mt][0], af[mt][1], af[mt][2], af[mt][3], b0, b1);
            }
        }
        CP_WAIT0();
        __syncthreads();
    }

    // ---- epilogue: BN (+sigmoid for a-channels) ----
#pragma unroll
    for (int mt = 0; mt < 2; mt++) {
#pragma unroll
        for (int nt = 0; nt < 8; nt++) {
#pragma unroll
            for (int e = 0; e < 4; e++) {
                int m = m0 + wm * 32 + mt * 16 + g + ((e >= 2) ? 8 : 0);
                int n = n0 + wn * 64 + nt * 8 + 2 * q + (e & 1);
                if (n >= 544) continue;
                int b = m / 25, p = m - b * 25;
                float val = acc[mt][nt][e];
                if (n < 32) {
                    float sc = bag[n] * rsqrtf(bav[n] + BN_EPS_F);
                    val = (val - bam[n]) * sc + bab[n];
                    g_a[b * 800 + p * 32 + n] = 1.f / (1.f + expf(-val));
                } else {
                    int co = n - 32;
                    float sc = bpg[co] * rsqrtf(bpv[co] + BN_EPS_F);
                    val = (val - bpm[co]) * sc + bpb[co];
                    g_pose[(size_t)m * 512 + co] = val;
                }
            }
        }
    }
}

// ---------------- EM routing with on-the-fly vote recompute ----------------
__global__ __launch_bounds__(640) void routing_k(
    const float* __restrict__ Wg,
    const float* __restrict__ beta_u, const float* __restrict__ beta_a,
    float* __restrict__ out)
{
    extern __shared__ float smf[];
    float* pose_T = smf;            // [16][800]
    float* r_sm   = smf + 12800;    // [10][800]
    float* au_sm  = r_sm + 8000;    // [800]
    float* part   = au_sm + 800;    // [20][33]
    float* mu_sm  = part + 660;     // [10][16]
    float* i2s_sm = mu_sm + 160;    // [10][16]
    float* ccst   = i2s_sm + 160;   // [10]
    float* aout   = ccst + 10;      // [10]

    int b = blockIdx.x;
    int tid = threadIdx.x;
    int w = tid >> 5;
    int lane = tid & 31;
    int c = w >> 1;
    int h = w & 1;

    for (int idx = tid; idx < 12800; idx += 640) {
        int i = idx >> 4, d = idx & 15;
        pose_T[d * 800 + i] =
            g_pose[(size_t)(b * 25 + (i >> 5)) * 512 + (i & 31) * 16 + d];
    }
    for (int i = tid; i < 800; i += 640) au_sm[i] = g_a[b * 800 + i];
    for (int idx = tid; idx < 8000; idx += 640) r_sm[idx] = 1.f;
    __syncthreads();

    const float lam_tab[3] = {0.0005f, 0.000975f, 0.00142625f};

    for (int iter = 0; iter < 3; iter++) {
        float T0 = 0.f, T1[16], T2[16];
#pragma unroll
        for (int d = 0; d < 16; d++) { T1[d] = 0.f; T2[d] = 0.f; }

        for (int i = h * 400 + lane; i < h * 400 + 400; i += 32) {
            float rw = r_sm[c * 800 + i] * au_sm[i];
            const float4* W4 = (const float4*)(Wg + ((size_t)i * 10 + c) * 16);
            float4 w0 = W4[0], w1 = W4[1], w2 = W4[2], w3 = W4[3];
            T0 += rw;
#pragma unroll
            for (int rr = 0; rr < 4; rr++) {
                float m0 = pose_T[(rr * 4 + 0) * 800 + i];
                float m1 = pose_T[(rr * 4 + 1) * 800 + i];
                float m2 = pose_T[(rr * 4 + 2) * 800 + i];
                float m3 = pose_T[(rr * 4 + 3) * 800 + i];
                float v0 = m0 * w0.x + m1 * w1.x + m2 * w2.x + m3 * w3.x;
                float v1 = m0 * w0.y + m1 * w1.y + m2 * w2.y + m3 * w3.y;
                float v2 = m0 * w0.z + m1 * w1.z + m2 * w2.z + m3 * w3.z;
                float v3 = m0 * w0.w + m1 * w1.w + m2 * w2.w + m3 * w3.w;
                T1[rr * 4 + 0] += rw * v0;  T2[rr * 4 + 0] += rw * v0 * v0;
                T1[rr * 4 + 1] += rw * v1;  T2[rr * 4 + 1] += rw * v1 * v1;
                T1[rr * 4 + 2] += rw * v2;  T2[rr * 4 + 2] += rw * v2 * v2;
                T1[rr * 4 + 3] += rw * v3;  T2[rr * 4 + 3] += rw * v3 * v3;
            }
        }
#pragma unroll
        for (int o = 16; o; o >>= 1) {
            T0 += __shfl_xor_sync(0xffffffffu, T0, o);
#pragma unroll
            for (int d = 0; d < 16; d++) {
                T1[d] += __shfl_xor_sync(0xffffffffu, T1[d], o);
                T2[d] += __shfl_xor_sync(0xffffffffu, T2[d], o);
            }
        }
        if (lane == 0) {
            float* pp = part + w * 33;
            pp[0] = T0;
#pragma unroll
            for (int d = 0; d < 16; d++) { pp[1 + d] = T1[d]; pp[17 + d] = T2[d]; }
        }
        __syncthreads();

        if (tid < 10) {
            int cc = tid;
            const float* pa = part + (2 * cc) * 33;
            const float* pb = part + (2 * cc + 1) * 33;
            float t0 = pa[0] + pb[0];
            float dn = 1.f / (t0 + EPS_F);
            float t = dn * t0;
            float bu = beta_u[cc];
            float cost = 0.f, lnp = 0.f;
#pragma unroll
            for (int d = 0; d < 16; d++) {
                float t1 = pa[1 + d] + pb[1 + d];
                float t2 = pa[17 + d] + pb[17 + d];
                float mu = dn * t1;
                float sig = fmaxf(dn * t2 - mu * mu * (2.f - t), 0.f) + EPS_F;
                mu_sm[cc * 16 + d] = mu;
                i2s_sm[cc * 16 + d] = 0.5f / sig;
                float lg = logf(sig);
                cost += bu + 0.5f * lg;
                lnp += -0.5f * logf(sig * LN2PI_F);
            }
            float lam = lam_tab[iter];
            float ao = 1.f / (1.f + expf(-lam * (beta_a[cc] - cost * t0)));
            aout[cc] = ao;
            ccst[cc] = lnp + logf(ao);
        }
        __syncthreads();

        if (iter < 2) {
            for (int i = tid; i < 800; i += 640) {
                float m[16];
#pragma unroll
                for (int d = 0; d < 16; d++) m[d] = pose_T[d * 800 + i];
                const float* Wr = Wg + (size_t)i * 160;
                float lp[10];
                float mx = -1e30f;
#pragma unroll
                for (int cc = 0; cc < 10; cc++) {
                    const float4* W4 = (const float4*)(Wr + cc * 16);
                    float4 w0 = W4[0], w1 = W4[1], w2 = W4[2], w3 = W4[3];
                    float s = 0.f;
#pragma unroll
                    for (int rr = 0; rr < 4; rr++) {
                        float m0 = m[rr * 4 + 0], m1 = m[rr * 4 + 1];
                        float m2 = m[rr * 4 + 2], m3 = m[rr * 4 + 3];
                        float v0 = m0 * w0.x + m1 * w1.x + m2 * w2.x + m3 * w3.x;
                        float v1 = m0 * w0.y + m1 * w1.y + m2 * w2.y + m3 * w3.y;
                        float v2 = m0 * w0.z + m1 * w1.z + m2 * w2.z + m3 * w3.z;
                        float v3 = m0 * w0.w + m1 * w1.w + m2 * w2.w + m3 * w3.w;
                        float d0 = v0 - mu_sm[cc * 16 + rr * 4 + 0];
                        float d1 = v1 - mu_sm[cc * 16 + rr * 4 + 1];
                        float d2 = v2 - mu_sm[cc * 16 + rr * 4 + 2];
                        float d3 = v3 - mu_sm[cc * 16 + rr * 4 + 3];
                        s += d0 * d0 * i2s_sm[cc * 16 + rr * 4 + 0];
                        s += d1 * d1 * i2s_sm[cc * 16 + rr * 4 + 1];
                        s += d2 * d2 * i2s_sm[cc * 16 + rr * 4 + 2];
                        s += d3 * d3 * i2s_sm[cc * 16 + rr * 4 + 3];
                    }
                    lp[cc] = ccst[cc] - s;
                    mx = fmaxf(mx, lp[cc]);
                }
                float sum = 0.f;
#pragma unroll
                for (int cc = 0; cc < 10; cc++) { lp[cc] = expf(lp[cc] - mx); sum += lp[cc]; }
                float inv = 1.f / sum;
#pragma unroll
                for (int cc = 0; cc < 10; cc++) r_sm[cc * 800 + i] = lp[cc] * inv;
            }
            __syncthreads();
        }
    }

    if (tid == 0) {
        float s = 0.f;
#pragma unroll
        for (int cc = 0; cc < 10; cc++) s += aout[cc];
        float ls = logf(s);
#pragma unroll
        for (int cc = 0; cc < 10; cc++)
            out[b * 10 + cc] = logf(aout[cc]) - ls;
    }
}

// ---------------- launcher ----------------
extern "C" void kernel_launch(void* const* d_in, const int* in_sizes, int n_in,
                              void* d_out, int out_size)
{
    const float* x      = (const float*)d_in[0];
    const float* w_a    = (const float*)d_in[1];
    const float* w_pose = (const float*)d_in[2];
    const float* bn_a_g = (const float*)d_in[3];
    const float* bn_a_b = (const float*)d_in[4];
    const float* bn_a_m = (const float*)d_in[5];
    const float* bn_a_v = (const float*)d_in[6];
    const float* bn_p_g = (const float*)d_in[7];
    const float* bn_p_b = (const float*)d_in[8];
    const float* bn_p_m = (const float*)d_in[9];
    const float* bn_p_v = (const float*)d_in[10];
    const float* W      = (const float*)d_in[11];
    const float* beta_u = (const float*)d_in[12];
    const float* beta_a = (const float*)d_in[13];
    float* out = (float*)d_out;

    const int gemm_smem = 4 * ASTG * (int)sizeof(__nv_bfloat16);  // 73728 B
    cudaFuncSetAttribute(gemm_bf16, cudaFuncAttributeMaxDynamicSharedMemorySize,
                         gemm_smem);
    cudaFuncSetAttribute(routing_k, cudaFuncAttributeMaxDynamicSharedMemorySize,
                         92 * 1024);

    dim3 gi(6400, 9);
    im2col_k<<<gi, 256>>>(x);

    wpack_k<<<(544 * 4608 / 4 + 255) / 256, 256>>>(w_a, w_pose);

    dim3 gg(50, 5);
    gemm_bf16<<<gg, 256, gemm_smem>>>(bn_a_g, bn_a_b, bn_a_m, bn_a_v,
                                      bn_p_g, bn_p_b, bn_p_m, bn_p_v);

    routing_k<<<256, 640, 92 * 1024>>>(W, beta_u, beta_a, out);
}